// round 9
// baseline (speedup 1.0000x reference)
#include <cuda_runtime.h>
#include <cuda_fp16.h>
#include <stdint.h>

#define SPLITK 148
#define KCHUNK 64
#define LTOT   256
#define DDIM   128

// scratch (allocation-free rule: __device__ globals)
__device__ float g_part[SPLITK * LTOT * DDIM];      // split-K partial numerators
__device__ float g_zpart[SPLITK * LTOT];            // split-K partial denominators

// ---------------------------------------------------------------------------
// helpers
// ---------------------------------------------------------------------------
__device__ __forceinline__ void ldsm_x4(uint32_t* r, uint32_t addr) {
    asm volatile("ldmatrix.sync.aligned.m8n8.x4.shared.b16 {%0,%1,%2,%3}, [%4];"
        : "=r"(r[0]), "=r"(r[1]), "=r"(r[2]), "=r"(r[3]) : "r"(addr));
}
__device__ __forceinline__ void ldsm_x4_t(uint32_t* r, uint32_t addr) {
    asm volatile("ldmatrix.sync.aligned.m8n8.x4.trans.shared.b16 {%0,%1,%2,%3}, [%4];"
        : "=r"(r[0]), "=r"(r[1]), "=r"(r[2]), "=r"(r[3]) : "r"(addr));
}
__device__ __forceinline__ void mma_fp16(float* c, const uint32_t* a, uint32_t b0, uint32_t b1) {
    asm volatile("mma.sync.aligned.m16n8k16.row.col.f32.f16.f16.f32 "
        "{%0,%1,%2,%3}, {%4,%5,%6,%7}, {%8,%9}, {%0,%1,%2,%3};"
        : "+f"(c[0]), "+f"(c[1]), "+f"(c[2]), "+f"(c[3])
        : "r"(a[0]), "r"(a[1]), "r"(a[2]), "r"(a[3]), "r"(b0), "r"(b1));
}
__device__ __forceinline__ uint2 pack_half4(float x, float y, float z, float w) {
    __half2 lo = __floats2half2_rn(x, y);
    __half2 hi = __floats2half2_rn(z, w);
    uint2 v;
    v.x = *(uint32_t*)&lo;
    v.y = *(uint32_t*)&hi;
    return v;
}

// ---------------------------------------------------------------------------
// Fused kernel, 2 syncs per 64-token chunk.
// iteration i:  compute { MLP(i) [16 warps, 16tok x 16j each] ;
//                         bigMMA(i-1) [warp = 32l x 64d, k=64] }
//               sync
//               staging { pfin(i) inline-exp; mp(i)=mask*p -> mA;
//                         fS(i+1) from regs; LDG mask(i+1), feats(i+2) }
//               sync
// grid = 148 x 512 (one wave, 1 CTA/SM).
// ---------------------------------------------------------------------------
#define MA_STR 72    // 64 k + 8 pad (halves)
#define G_STR  136   // 128 d + 8 pad (halves)
#define W1_STR 72    // 64 j + 8 pad (halves)
#define MA_HALVES (LTOT*MA_STR)     // 18432 (single buffer)
#define G_HALVES  (KCHUNK*G_STR)    // 8704 (x2 buffers)
#define SM2_BYTES ((MA_HALVES + 2*G_HALVES + 128*W1_STR)*2 + (LTOT*16 + 4*KCHUNK)*4)

__global__ __launch_bounds__(512, 1) void k2_fused(
    const float* __restrict__ feats, const float* __restrict__ mask,
    const float* __restrict__ W1, const float* __restrict__ b1,
    const float* __restrict__ W2, const float* __restrict__ b2,
    int B, int cps)
{
    extern __shared__ char smraw[];
    __half* mA   = (__half*)smraw;                   // [256 l][72]
    __half* fS   = mA + MA_HALVES;                   // 2 x [64 tok][136]
    __half* wS   = fS + 2*G_HALVES;                  // [128 k][72]
    float*  zsm  = (float*)(wS + 128*W1_STR);        // [256][16]
    float*  praw = zsm + LTOT*16;                    // [4 jg][64 tok]

    int tid  = threadIdx.x;
    int y    = blockIdx.x;
    int wid  = tid >> 5, lane = tid & 31;
    int wm   = wid & 7, wn = wid >> 3;       // big MMA mapping
    int tokg = wid & 3, jg = wid >> 2;       // MLP mapping (16 tok x 16 j)

    uint32_t mA_s = (uint32_t)__cvta_generic_to_shared(mA);
    uint32_t fS_s = (uint32_t)__cvta_generic_to_shared(fS);
    uint32_t wS_s = (uint32_t)__cvta_generic_to_shared(wS);

    float acc[2][8][4];
    #pragma unroll
    for (int mt = 0; mt < 2; mt++)
        #pragma unroll
        for (int nt = 0; nt < 8; nt++)
            #pragma unroll
            for (int e = 0; e < 4; e++) acc[mt][nt][e] = 0.f;
    float zacc[8];
    #pragma unroll
    for (int i = 0; i < 8; i++) zacc[i] = 0.f;

    // per-warp MLP constants: 4 j values per thread (2 np blocks x 2)
    int j0a = jg*16 + (lane & 3)*2, j0b = j0a + 8;
    float b1a = __ldg(b1 + j0a), b1b = __ldg(b1 + j0a + 1);
    float b1c = __ldg(b1 + j0b), b1d = __ldg(b1 + j0b + 1);
    float w2a = __ldg(W2 + j0a), w2b = __ldg(W2 + j0a + 1);
    float w2c = __ldg(W2 + j0b), w2d = __ldg(W2 + j0b + 1);
    float b2v = __ldg(b2);

    // staging maps
    int mrow = tid >> 4, mc4 = tid & 15;     // mask/mp: l rows mrow+32i (i<8), k-cols mc4*4
    // feats: idx = tid + ii*512 (ii<4): tok idx>>5, d-col (idx&31)*4

    uint2 m4[8], f4[4];                      // packed fp16 prefetch regs
    int kb0 = y * cps * KCHUNK;

    // ---- prologue ----
    #pragma unroll
    for (int ii = 0; ii < 4; ii++) {         // W1 -> wS fp16
        int idx = tid + ii*512;
        int row = idx >> 4, c4 = idx & 15;
        float4 v = ((const float4*)W1)[idx];
        *(uint2*)(wS + row*W1_STR + c4*4) = pack_half4(v.x, v.y, v.z, v.w);
    }
    #pragma unroll
    for (int ii = 0; ii < 4; ii++) {         // feats(0) -> fS[0] direct
        int idx = tid + ii*512;
        int tok = kb0 + (idx >> 5);
        float4 v = (tok < B) ? ((const float4*)(feats + (size_t)tok*DDIM))[idx & 31]
                             : make_float4(0.f, 0.f, 0.f, 0.f);
        *(uint2*)(fS + (idx >> 5)*G_STR + (idx & 31)*4) = pack_half4(v.x, v.y, v.z, v.w);
    }
    {   // LDG mask(0) -> m4 (packed), feats(1) -> f4 (packed)
        int gk = kb0 + mc4*4;
        #pragma unroll
        for (int ii = 0; ii < 8; ii++) {
            float4 v = (gk < B) ? *((const float4*)(mask + (size_t)(mrow + ii*32)*B + gk))
                                : make_float4(0.f, 0.f, 0.f, 0.f);
            m4[ii] = pack_half4(v.x, v.y, v.z, v.w);
        }
        #pragma unroll
        for (int ii = 0; ii < 4; ii++) {
            int idx = tid + ii*512;
            int tok = kb0 + KCHUNK + (idx >> 5);
            float4 v = (tok < B && cps > 1)
                     ? ((const float4*)(feats + (size_t)tok*DDIM))[idx & 31]
                     : make_float4(0.f, 0.f, 0.f, 0.f);
            f4[ii] = pack_half4(v.x, v.y, v.z, v.w);
        }
    }
    __syncthreads();

    // ---- main loop: i = chunk index (one extra iteration drains bigMMA) ----
    for (int i = 0; i <= cps; i++) {
        // === compute phase ===
        if (i < cps) {
            // MLP(i) on fS[i&1]: warp = 16 tok x 16 j, k=128
            uint32_t fb = fS_s + (uint32_t)((i & 1) * G_HALVES * 2);
            float mc0[4] = {0.f,0.f,0.f,0.f};
            float mc1[4] = {0.f,0.f,0.f,0.f};
            #pragma unroll
            for (int ks = 0; ks < 8; ks++) {
                uint32_t a[4];
                ldsm_x4(a, fb + (uint32_t)(((tokg*16 + (lane & 15))*G_STR
                                  + ks*16 + ((lane >> 4) << 3)) * 2));
                uint32_t bb[4];
                ldsm_x4_t(bb, wS_s + (uint32_t)(((ks*16 + (lane & 15))*W1_STR
                                  + jg*16 + ((lane >> 4) << 3)) * 2));
                mma_fp16(mc0, a, bb[0], bb[1]);
                mma_fp16(mc1, a, bb[2], bb[3]);
            }
            float s0 = tanhf(mc0[0] + b1a)*w2a + tanhf(mc0[1] + b1b)*w2b
                     + tanhf(mc1[0] + b1c)*w2c + tanhf(mc1[1] + b1d)*w2d;
            float s1 = tanhf(mc0[2] + b1a)*w2a + tanhf(mc0[3] + b1b)*w2b
                     + tanhf(mc1[2] + b1c)*w2c + tanhf(mc1[3] + b1d)*w2d;
            s0 += __shfl_xor_sync(0xffffffffu, s0, 1);
            s0 += __shfl_xor_sync(0xffffffffu, s0, 2);
            s1 += __shfl_xor_sync(0xffffffffu, s1, 1);
            s1 += __shfl_xor_sync(0xffffffffu, s1, 2);
            if ((lane & 3) == 0) {
                int t = tokg*16 + (lane >> 2);
                praw[jg*64 + t]     = s0;
                praw[jg*64 + t + 8] = s1;
            }
        }
        if (i >= 1) {
            // bigMMA(i-1): mA x fS[(i-1)&1], k=64
            uint32_t fb = fS_s + (uint32_t)(((i - 1) & 1) * G_HALVES * 2);
            #pragma unroll
            for (int ks = 0; ks < 4; ks++) {
                uint32_t a[2][4];
                #pragma unroll
                for (int mt = 0; mt < 2; mt++)
                    ldsm_x4(a[mt], mA_s + (uint32_t)(((wm*32 + mt*16 + (lane & 15)) * MA_STR
                                     + ks*16 + ((lane >> 4) << 3)) * 2));
                #pragma unroll
                for (int np = 0; np < 4; np++) {
                    uint32_t b[4];
                    ldsm_x4_t(b, fb + (uint32_t)(((ks*16 + (lane & 15)) * G_STR
                                     + wn*64 + np*16 + ((lane >> 4) << 3)) * 2));
                    #pragma unroll
                    for (int mt = 0; mt < 2; mt++) {
                        mma_fp16(acc[mt][np*2],     a[mt], b[0], b[1]);
                        mma_fp16(acc[mt][np*2 + 1], a[mt], b[2], b[3]);
                    }
                }
            }
        }
        __syncthreads();               // praw(i) visible; mA/fS free for restage
        if (i == cps) break;

        // === staging phase (chunk i) ===
        // inline pfin: p for this thread's 4 k-tokens
        float pl[4];
        #pragma unroll
        for (int j = 0; j < 4; j++) {
            int t = mc4*4 + j;
            pl[j] = expf(praw[t] + praw[64 + t] + praw[128 + t] + praw[192 + t] + b2v);
        }
        __half2 ph01 = __floats2half2_rn(pl[0], pl[1]);
        __half2 ph23 = __floats2half2_rn(pl[2], pl[3]);

        // mp(i) = mask * p -> mA; Z fused (m is exact 0/1 in fp16)
        #pragma unroll
        for (int ii = 0; ii < 8; ii++) {
            uint2 mr = m4[ii];
            __half2 m01 = *(__half2*)&mr.x;
            __half2 m23 = *(__half2*)&mr.y;
            __half2 mp01 = __hmul2(m01, ph01);
            __half2 mp23 = __hmul2(m23, ph23);
            uint2 st;
            st.x = *(uint32_t*)&mp01;
            st.y = *(uint32_t*)&mp23;
            *(uint2*)(mA + (mrow + ii*32)*MA_STR + mc4*4) = st;
            float2 a01 = __half22float2(m01);
            float2 a23 = __half22float2(m23);
            zacc[ii] += a01.x*pl[0] + a01.y*pl[1] + a23.x*pl[2] + a23.y*pl[3];
        }

        // stage fS(i+1) from regs
        if (i + 1 < cps) {
            __half* fd = fS + ((i + 1) & 1) * G_HALVES;
            #pragma unroll
            for (int ii = 0; ii < 4; ii++) {
                int idx = tid + ii*512;
                *(uint2*)(fd + (idx >> 5)*G_STR + (idx & 31)*4) = f4[ii];
            }
        }
        // LDG mask(i+1)
        if (i + 1 < cps) {
            int gk = kb0 + (i + 1)*KCHUNK + mc4*4;
            #pragma unroll
            for (int ii = 0; ii < 8; ii++) {
                float4 v = (gk < B) ? *((const float4*)(mask + (size_t)(mrow + ii*32)*B + gk))
                                    : make_float4(0.f, 0.f, 0.f, 0.f);
                m4[ii] = pack_half4(v.x, v.y, v.z, v.w);
            }
        }
        // LDG feats(i+2)
        if (i + 2 < cps) {
            #pragma unroll
            for (int ii = 0; ii < 4; ii++) {
                int idx = tid + ii*512;
                int tok = kb0 + (i + 2)*KCHUNK + (idx >> 5);
                float4 v = (tok < B) ? ((const float4*)(feats + (size_t)tok*DDIM))[idx & 31]
                                     : make_float4(0.f, 0.f, 0.f, 0.f);
                f4[ii] = pack_half4(v.x, v.y, v.z, v.w);
            }
        }
        __syncthreads();               // mA(i), fS(i+1) visible
    }

    // ---- deterministic Z reduction ----
    #pragma unroll
    for (int ii = 0; ii < 8; ii++)
        zsm[(mrow + ii*32)*16 + mc4] = zacc[ii];
    __syncthreads();
    if (tid < LTOT) {
        float z = 0.f;
        #pragma unroll
        for (int j = 0; j < 16; j++) z += zsm[tid*16 + j];
        g_zpart[y*LTOT + tid] = z;
    }

    // ---- write numerator partials ----
    #pragma unroll
    for (int mt = 0; mt < 2; mt++) {
        #pragma unroll
        for (int nt = 0; nt < 8; nt++) {
            int grow = wm*32 + mt*16 + (lane >> 2);
            int gcol = wn*64 + nt*8 + (lane & 3)*2;
            size_t o0 = ((size_t)y*LTOT + grow) * DDIM + gcol;
            size_t o1 = ((size_t)y*LTOT + grow + 8) * DDIM + gcol;
            *(float2*)(g_part + o0) = make_float2(acc[mt][nt][0], acc[mt][nt][1]);
            *(float2*)(g_part + o1) = make_float2(acc[mt][nt][2], acc[mt][nt][3]);
        }
    }
}

// ---------------------------------------------------------------------------
// Kernel 3: parallel reduce. 512 blocks (l x d-half) x 256 thr, 4 y-groups.
// ---------------------------------------------------------------------------
__global__ __launch_bounds__(256, 4) void k3_reduce(float* __restrict__ out)
{
    __shared__ float nsm[4][64];
    __shared__ float zsm4[4];

    int l  = blockIdx.x >> 1;
    int dh = blockIdx.x & 1;
    int tid = threadIdx.x;
    int g  = tid >> 6;
    int dl = tid & 63;
    int d  = dh*64 + dl;

    int y0 = g * 37, y1 = y0 + 37;   // 4*37 = 148
    float num = 0.f, z = 0.f;
    #pragma unroll 4
    for (int yy = y0; yy < y1; yy++) {
        num += g_part[((size_t)yy*LTOT + l) * DDIM + d];
        z   += g_zpart[yy*LTOT + l];
    }
    nsm[g][dl] = num;
    if (dl == 0) zsm4[g] = z;
    __syncthreads();

    if (g == 0) {
        float n = nsm[0][dl] + nsm[1][dl] + nsm[2][dl] + nsm[3][dl];
        float zz = zsm4[0] + zsm4[1] + zsm4[2] + zsm4[3];
        out[l*DDIM + d] = (zz > 0.f) ? n / zz : 0.f;
    }
}

// ---------------------------------------------------------------------------
extern "C" void kernel_launch(void* const* d_in, const int* in_sizes, int n_in,
                              void* d_out, int out_size)
{
    const float* feats = (const float*)d_in[0];
    const float* mask  = (const float*)d_in[1];
    const float* W1    = (const float*)d_in[2];
    const float* b1    = (const float*)d_in[3];
    const float* W2    = (const float*)d_in[4];
    const float* b2    = (const float*)d_in[5];
    float* out = (float*)d_out;

    int B = in_sizes[0] / DDIM;           // 200000
    int totalChunks = (B + KCHUNK - 1) / KCHUNK;
    int cps = (totalChunks + SPLITK - 1) / SPLITK;

    cudaFuncSetAttribute(k2_fused, cudaFuncAttributeMaxDynamicSharedMemorySize, SM2_BYTES);

    k2_fused<<<SPLITK, 512, SM2_BYTES>>>(feats, mask, W1, b1, W2, b2, B, cps);

    k3_reduce<<<LTOT*2, 256>>>(out);
}

// round 10
// speedup vs baseline: 1.0873x; 1.0873x over previous
#include <cuda_runtime.h>
#include <cuda_fp16.h>
#include <stdint.h>

#define SPLITK 148
#define KCHUNK 64
#define LTOT   256
#define DDIM   128

// scratch (allocation-free rule: __device__ globals)
__device__ float g_p[200064];                       // exp(logits) per token
__device__ float g_part[SPLITK * LTOT * DDIM];      // split-K partial numerators
__device__ float g_zpart[SPLITK * LTOT];            // split-K partial denominators

// ---------------------------------------------------------------------------
// helpers
// ---------------------------------------------------------------------------
__device__ __forceinline__ void ldsm_x4(uint32_t* r, uint32_t addr) {
    asm volatile("ldmatrix.sync.aligned.m8n8.x4.shared.b16 {%0,%1,%2,%3}, [%4];"
        : "=r"(r[0]), "=r"(r[1]), "=r"(r[2]), "=r"(r[3]) : "r"(addr));
}
__device__ __forceinline__ void ldsm_x4_t(uint32_t* r, uint32_t addr) {
    asm volatile("ldmatrix.sync.aligned.m8n8.x4.trans.shared.b16 {%0,%1,%2,%3}, [%4];"
        : "=r"(r[0]), "=r"(r[1]), "=r"(r[2]), "=r"(r[3]) : "r"(addr));
}
__device__ __forceinline__ void mma_fp16(float* c, const uint32_t* a, uint32_t b0, uint32_t b1) {
    asm volatile("mma.sync.aligned.m16n8k16.row.col.f32.f16.f16.f32 "
        "{%0,%1,%2,%3}, {%4,%5,%6,%7}, {%8,%9}, {%0,%1,%2,%3};"
        : "+f"(c[0]), "+f"(c[1]), "+f"(c[2]), "+f"(c[3])
        : "r"(a[0]), "r"(a[1]), "r"(a[2]), "r"(a[3]), "r"(b0), "r"(b1));
}
__device__ __forceinline__ uint2 pack_half4(float x, float y, float z, float w) {
    __half2 lo = __floats2half2_rn(x, y);
    __half2 hi = __floats2half2_rn(z, w);
    uint2 v;
    v.x = *(uint32_t*)&lo;
    v.y = *(uint32_t*)&hi;
    return v;
}

// ---------------------------------------------------------------------------
// Kernel 1: p = exp(W2 . tanh(f @ W1 + b1) + b2), fp16 MMA (round-7 version).
// ---------------------------------------------------------------------------
#define A1_STR 136
#define W1_STR 72
#define SM1_BYTES ((128*A1_STR + 128*W1_STR) * 2)

__global__ __launch_bounds__(256, 2) void k1_logits(
    const float* __restrict__ feats, const float* __restrict__ W1,
    const float* __restrict__ b1, const float* __restrict__ W2,
    const float* __restrict__ b2, int B)
{
    extern __shared__ __half sm1[];
    __half* aS = sm1;                  // [128 tok][136]
    __half* wS = sm1 + 128*A1_STR;     // [128 k][72]

    int tid = threadIdx.x;
    int tok0 = blockIdx.x * 128;
    int wid = tid >> 5, lane = tid & 31;

    #pragma unroll
    for (int i = 0; i < 16; i++) {
        int idx = tid + i*256;
        int row = idx >> 5, c4 = idx & 31;
        int tok = tok0 + row;
        float4 v = make_float4(0.f, 0.f, 0.f, 0.f);
        if (tok < B) v = ((const float4*)(feats + (size_t)tok*DDIM))[c4];
        *(uint2*)(aS + row*A1_STR + c4*4) = pack_half4(v.x, v.y, v.z, v.w);
    }
    #pragma unroll
    for (int i = 0; i < 8; i++) {
        int idx = tid + i*256;
        int row = idx >> 4, c4 = idx & 15;
        float4 v = ((const float4*)W1)[idx];
        *(uint2*)(wS + row*W1_STR + c4*4) = pack_half4(v.x, v.y, v.z, v.w);
    }
    __syncthreads();

    uint32_t aS_s = (uint32_t)__cvta_generic_to_shared(aS);
    uint32_t wS_s = (uint32_t)__cvta_generic_to_shared(wS);

    float acc[8][4];
    #pragma unroll
    for (int nt = 0; nt < 8; nt++)
        #pragma unroll
        for (int e = 0; e < 4; e++) acc[nt][e] = 0.f;

    #pragma unroll
    for (int ks = 0; ks < 8; ks++) {
        uint32_t a[4];
        ldsm_x4(a, aS_s + (uint32_t)(((wid*16 + (lane & 15)) * A1_STR
                          + ks*16 + ((lane >> 4) << 3)) * 2));
        #pragma unroll
        for (int np = 0; np < 4; np++) {
            uint32_t b[4];
            ldsm_x4_t(b, wS_s + (uint32_t)(((ks*16 + (lane & 15)) * W1_STR
                              + np*16 + ((lane >> 4) << 3)) * 2));
            mma_fp16(acc[np*2],     a, b[0], b[1]);
            mma_fp16(acc[np*2 + 1], a, b[2], b[3]);
        }
    }

    float s0 = 0.f, s1 = 0.f;
    #pragma unroll
    for (int nt = 0; nt < 8; nt++) {
        int j0 = nt*8 + (lane & 3)*2;
        float b1a = __ldg(b1 + j0), b1b = __ldg(b1 + j0 + 1);
        float w2a = __ldg(W2 + j0), w2b = __ldg(W2 + j0 + 1);
        s0 += tanhf(acc[nt][0] + b1a) * w2a + tanhf(acc[nt][1] + b1b) * w2b;
        s1 += tanhf(acc[nt][2] + b1a) * w2a + tanhf(acc[nt][3] + b1b) * w2b;
    }
    #pragma unroll
    for (int m = 1; m <= 2; m <<= 1) {
        s0 += __shfl_xor_sync(0xffffffffu, s0, m);
        s1 += __shfl_xor_sync(0xffffffffu, s1, m);
    }
    if ((lane & 3) == 0) {
        float bb2 = __ldg(b2);
        int r = lane >> 2;
        int tok = tok0 + wid*16 + r;
        if (tok < B)     g_p[tok]     = expf(s0 + bb2);
        if (tok + 8 < B) g_p[tok + 8] = expf(s1 + bb2);
    }
}

// ---------------------------------------------------------------------------
// Kernel 2: split-K fp16 MMA, KCHUNK=64, one 512-thread CTA per split, all
// 256 l. Packed-fp16 register prefetch, double-buffered smem, 1 sync/chunk.
// warp = 32 l x 64 d, k=64 per chunk (22 chunks). NO fusion (proven loser).
// ---------------------------------------------------------------------------
#define MA_STR 72    // 64 k + 8 pad (halves)
#define G_STR  136   // 128 d + 8 pad (halves)
#define MA_HALVES (LTOT*MA_STR)     // 18432
#define G_HALVES  (KCHUNK*G_STR)    // 8704
#define SM2_BYTES ((2*MA_HALVES + 2*G_HALVES)*2 + LTOT*16*4)

__global__ __launch_bounds__(512, 1) void k2_mma(
    const float* __restrict__ feats, const float* __restrict__ mask,
    int B, int cps)
{
    extern __shared__ char smraw[];
    __half* mA  = (__half*)smraw;                    // 2 x [256 l][72]
    __half* fS  = mA + 2*MA_HALVES;                  // 2 x [64 tok][136]
    float*  zsm = (float*)(fS + 2*G_HALVES);         // [256][16]

    int tid  = threadIdx.x;
    int y    = blockIdx.x;
    int wid  = tid >> 5, lane = tid & 31;
    int wm   = wid & 7, wn = wid >> 3;

    float acc[2][8][4];
    #pragma unroll
    for (int mt = 0; mt < 2; mt++)
        #pragma unroll
        for (int nt = 0; nt < 8; nt++)
            #pragma unroll
            for (int e = 0; e < 4; e++) acc[mt][nt][e] = 0.f;
    float zacc[8];
    #pragma unroll
    for (int i = 0; i < 8; i++) zacc[i] = 0.f;

    uint32_t mA_s = (uint32_t)__cvta_generic_to_shared(mA);
    uint32_t fS_s = (uint32_t)__cvta_generic_to_shared(fS);

    // staging maps
    int mrow = tid >> 4, mc4 = tid & 15;     // mask: l rows mrow+32i (i<8), k-col mc4*4
    // feats: idx = tid + ii*512 (ii<4): tok idx>>5, d-col (idx&31)*4

    uint2 m4[8], f4[4];                      // packed fp16 prefetch
    float4 p4;                               // fp32 p for this thread's 4 k
    int kb0 = y * cps * KCHUNK;

    // prologue: chunk 0
    {
        int gk = kb0 + mc4*4;
        p4 = (gk < B) ? *((const float4*)(g_p + gk)) : make_float4(0.f,0.f,0.f,0.f);
        #pragma unroll
        for (int ii = 0; ii < 8; ii++) {
            float4 v = (gk < B) ? *((const float4*)(mask + (size_t)(mrow + ii*32)*B + gk))
                                : make_float4(0.f, 0.f, 0.f, 0.f);
            m4[ii] = pack_half4(v.x, v.y, v.z, v.w);
        }
        #pragma unroll
        for (int ii = 0; ii < 4; ii++) {
            int idx = tid + ii*512;
            int tok = kb0 + (idx >> 5);
            float4 v = (tok < B) ? ((const float4*)(feats + (size_t)tok*DDIM))[idx & 31]
                                 : make_float4(0.f, 0.f, 0.f, 0.f);
            f4[ii] = pack_half4(v.x, v.y, v.z, v.w);
        }
    }

    for (int c = 0; c < cps; c++) {
        __half* mA_c = mA + (c & 1) * MA_HALVES;
        __half* fS_c = fS + (c & 1) * G_HALVES;

        // stage mp(c) = mask * p -> fp16 (m exact 0/1); Z fused in fp32
        __half2 ph01 = __floats2half2_rn(p4.x, p4.y);
        __half2 ph23 = __floats2half2_rn(p4.z, p4.w);
        #pragma unroll
        for (int ii = 0; ii < 8; ii++) {
            uint2 mr = m4[ii];
            __half2 m01 = *(__half2*)&mr.x;
            __half2 m23 = *(__half2*)&mr.y;
            __half2 mp01 = __hmul2(m01, ph01);
            __half2 mp23 = __hmul2(m23, ph23);
            uint2 st;
            st.x = *(uint32_t*)&mp01;
            st.y = *(uint32_t*)&mp23;
            *(uint2*)(mA_c + (mrow + ii*32)*MA_STR + mc4*4) = st;
            float2 a01 = __half22float2(m01);
            float2 a23 = __half22float2(m23);
            zacc[ii] += a01.x*p4.x + a01.y*p4.y + a23.x*p4.z + a23.y*p4.w;
        }
        // stage feats(c) packed regs -> fS
        #pragma unroll
        for (int ii = 0; ii < 4; ii++) {
            int idx = tid + ii*512;
            *(uint2*)(fS_c + (idx >> 5)*G_STR + (idx & 31)*4) = f4[ii];
        }

        // prefetch chunk c+1
        if (c + 1 < cps) {
            int kb2 = kb0 + (c + 1)*KCHUNK;
            int gk = kb2 + mc4*4;
            p4 = (gk < B) ? *((const float4*)(g_p + gk)) : make_float4(0.f,0.f,0.f,0.f);
            #pragma unroll
            for (int ii = 0; ii < 8; ii++) {
                float4 v = (gk < B) ? *((const float4*)(mask + (size_t)(mrow + ii*32)*B + gk))
                                    : make_float4(0.f, 0.f, 0.f, 0.f);
                m4[ii] = pack_half4(v.x, v.y, v.z, v.w);
            }
            #pragma unroll
            for (int ii = 0; ii < 4; ii++) {
                int idx = tid + ii*512;
                int tok = kb2 + (idx >> 5);
                float4 v = (tok < B) ? ((const float4*)(feats + (size_t)tok*DDIM))[idx & 31]
                                     : make_float4(0.f, 0.f, 0.f, 0.f);
                f4[ii] = pack_half4(v.x, v.y, v.z, v.w);
            }
        }
        __syncthreads();   // staged buffers visible; ldmatrix(c-1) complete

        // MMA over chunk c (k=64)
        uint32_t mA_b = mA_s + (uint32_t)((c & 1) * MA_HALVES * 2);
        uint32_t fS_b = fS_s + (uint32_t)((c & 1) * G_HALVES * 2);
        #pragma unroll
        for (int ks = 0; ks < 4; ks++) {
            uint32_t a[2][4];
            #pragma unroll
            for (int mt = 0; mt < 2; mt++)
                ldsm_x4(a[mt], mA_b + (uint32_t)(((wm*32 + mt*16 + (lane & 15)) * MA_STR
                                 + ks*16 + ((lane >> 4) << 3)) * 2));
            #pragma unroll
            for (int np = 0; np < 4; np++) {
                uint32_t b[4];
                ldsm_x4_t(b, fS_b + (uint32_t)(((ks*16 + (lane & 15)) * G_STR
                                 + wn*64 + np*16 + ((lane >> 4) << 3)) * 2));
                #pragma unroll
                for (int mt = 0; mt < 2; mt++) {
                    mma_fp16(acc[mt][np*2],     a[mt], b[0], b[1]);
                    mma_fp16(acc[mt][np*2 + 1], a[mt], b[2], b[3]);
                }
            }
        }
    }

    // deterministic Z reduction
    __syncthreads();
    #pragma unroll
    for (int ii = 0; ii < 8; ii++)
        zsm[(mrow + ii*32)*16 + mc4] = zacc[ii];
    __syncthreads();
    if (tid < LTOT) {
        float z = 0.f;
        #pragma unroll
        for (int j = 0; j < 16; j++) z += zsm[tid*16 + j];
        g_zpart[y*LTOT + tid] = z;
    }

    // write numerator partials
    #pragma unroll
    for (int mt = 0; mt < 2; mt++) {
        #pragma unroll
        for (int nt = 0; nt < 8; nt++) {
            int grow = wm*32 + mt*16 + (lane >> 2);
            int gcol = wn*64 + nt*8 + (lane & 3)*2;
            size_t o0 = ((size_t)y*LTOT + grow) * DDIM + gcol;
            size_t o1 = ((size_t)y*LTOT + grow + 8) * DDIM + gcol;
            *(float2*)(g_part + o0) = make_float2(acc[mt][nt][0], acc[mt][nt][1]);
            *(float2*)(g_part + o1) = make_float2(acc[mt][nt][2], acc[mt][nt][3]);
        }
    }
}

// ---------------------------------------------------------------------------
// Kernel 3: parallel reduce, FULL unroll so all 37 loads are in flight at
// once (round-9 version serialized in batches of 4 -> latency-bound).
// ---------------------------------------------------------------------------
__global__ __launch_bounds__(512, 2) void k3_reduce(float* __restrict__ out)
{
    __shared__ float nsm[4][DDIM];
    __shared__ float zsm4[4];

    int l = blockIdx.x;
    int tid = threadIdx.x;
    int g = tid >> 7;
    int d = tid & 127;

    const float* pbase = g_part + ((size_t)(g*37)*LTOT + l) * DDIM + d;
    const float* zbase = g_zpart + (g*37)*LTOT + l;

    float n0 = 0.f, n1 = 0.f, z0 = 0.f, z1 = 0.f;
    #pragma unroll
    for (int yy = 0; yy < 37; yy += 2) {
        n0 += pbase[(size_t)yy * LTOT * DDIM];
        z0 += zbase[yy * LTOT];
    }
    #pragma unroll
    for (int yy = 1; yy < 37; yy += 2) {
        n1 += pbase[(size_t)yy * LTOT * DDIM];
        z1 += zbase[yy * LTOT];
    }
    nsm[g][d] = n0 + n1;
    if (d == 0) zsm4[g] = z0 + z1;
    __syncthreads();

    if (g == 0) {
        float n = nsm[0][d] + nsm[1][d] + nsm[2][d] + nsm[3][d];
        float zz = zsm4[0] + zsm4[1] + zsm4[2] + zsm4[3];
        out[l*DDIM + d] = (zz > 0.f) ? n / zz : 0.f;
    }
}

// ---------------------------------------------------------------------------
extern "C" void kernel_launch(void* const* d_in, const int* in_sizes, int n_in,
                              void* d_out, int out_size)
{
    const float* feats = (const float*)d_in[0];
    const float* mask  = (const float*)d_in[1];
    const float* W1    = (const float*)d_in[2];
    const float* b1    = (const float*)d_in[3];
    const float* W2    = (const float*)d_in[4];
    const float* b2    = (const float*)d_in[5];
    float* out = (float*)d_out;

    int B = in_sizes[0] / DDIM;           // 200000
    int totalChunks = (B + KCHUNK - 1) / KCHUNK;
    int cps = (totalChunks + SPLITK - 1) / SPLITK;

    cudaFuncSetAttribute(k1_logits, cudaFuncAttributeMaxDynamicSharedMemorySize, SM1_BYTES);
    cudaFuncSetAttribute(k2_mma,    cudaFuncAttributeMaxDynamicSharedMemorySize, SM2_BYTES);

    int g1 = (B + 127) / 128;
    k1_logits<<<g1, 256, SM1_BYTES>>>(feats, W1, b1, W2, b2, B);

    k2_mma<<<SPLITK, 512, SM2_BYTES>>>(feats, mask, B, cps);

    k3_reduce<<<LTOT, 512>>>(out);
}

// round 11
// speedup vs baseline: 1.4348x; 1.3196x over previous
#include <cuda_runtime.h>
#include <cuda_fp16.h>
#include <stdint.h>

#define SPLITK 148
#define KCHUNK 32
#define LTOT   256
#define DDIM   128

// scratch (allocation-free rule: __device__ globals)
__device__ float g_p[200064];                       // exp(logits) per token
__device__ float g_part[SPLITK * LTOT * DDIM];      // split-K partial numerators
__device__ float g_zpart[SPLITK * LTOT];            // split-K partial denominators

// ---------------------------------------------------------------------------
// helpers
// ---------------------------------------------------------------------------
__device__ __forceinline__ void ldsm_x4(uint32_t* r, uint32_t addr) {
    asm volatile("ldmatrix.sync.aligned.m8n8.x4.shared.b16 {%0,%1,%2,%3}, [%4];"
        : "=r"(r[0]), "=r"(r[1]), "=r"(r[2]), "=r"(r[3]) : "r"(addr));
}
__device__ __forceinline__ void ldsm_x4_t(uint32_t* r, uint32_t addr) {
    asm volatile("ldmatrix.sync.aligned.m8n8.x4.trans.shared.b16 {%0,%1,%2,%3}, [%4];"
        : "=r"(r[0]), "=r"(r[1]), "=r"(r[2]), "=r"(r[3]) : "r"(addr));
}
__device__ __forceinline__ void mma_fp16(float* c, const uint32_t* a, uint32_t b0, uint32_t b1) {
    asm volatile("mma.sync.aligned.m16n8k16.row.col.f32.f16.f16.f32 "
        "{%0,%1,%2,%3}, {%4,%5,%6,%7}, {%8,%9}, {%0,%1,%2,%3};"
        : "+f"(c[0]), "+f"(c[1]), "+f"(c[2]), "+f"(c[3])
        : "r"(a[0]), "r"(a[1]), "r"(a[2]), "r"(a[3]), "r"(b0), "r"(b1));
}
__device__ __forceinline__ uint2 pack_half4(float x, float y, float z, float w) {
    __half2 lo = __floats2half2_rn(x, y);
    __half2 hi = __floats2half2_rn(z, w);
    uint2 v;
    v.x = *(uint32_t*)&lo;
    v.y = *(uint32_t*)&hi;
    return v;
}

// ---------------------------------------------------------------------------
// Kernel 1: p = exp(W2 . tanh(f @ W1 + b1) + b2), fp16 MMA.
// launch_bounds(256,3): 85-reg cap -> 24 warps/SM for latency hiding.
// ---------------------------------------------------------------------------
#define A1_STR 136
#define W1_STR 72
#define SM1_BYTES ((128*A1_STR + 128*W1_STR) * 2)

__global__ __launch_bounds__(256, 3) void k1_logits(
    const float* __restrict__ feats, const float* __restrict__ W1,
    const float* __restrict__ b1, const float* __restrict__ W2,
    const float* __restrict__ b2, int B)
{
    extern __shared__ __half sm1[];
    __half* aS = sm1;                  // [128 tok][136]
    __half* wS = sm1 + 128*A1_STR;     // [128 k][72]

    int tid = threadIdx.x;
    int tok0 = blockIdx.x * 128;
    int wid = tid >> 5, lane = tid & 31;

    #pragma unroll
    for (int i = 0; i < 16; i++) {
        int idx = tid + i*256;
        int row = idx >> 5, c4 = idx & 31;
        int tok = tok0 + row;
        float4 v = make_float4(0.f, 0.f, 0.f, 0.f);
        if (tok < B) v = ((const float4*)(feats + (size_t)tok*DDIM))[c4];
        *(uint2*)(aS + row*A1_STR + c4*4) = pack_half4(v.x, v.y, v.z, v.w);
    }
    #pragma unroll
    for (int i = 0; i < 8; i++) {
        int idx = tid + i*256;
        int row = idx >> 4, c4 = idx & 15;
        float4 v = ((const float4*)W1)[idx];
        *(uint2*)(wS + row*W1_STR + c4*4) = pack_half4(v.x, v.y, v.z, v.w);
    }
    __syncthreads();

    uint32_t aS_s = (uint32_t)__cvta_generic_to_shared(aS);
    uint32_t wS_s = (uint32_t)__cvta_generic_to_shared(wS);

    float acc[8][4];
    #pragma unroll
    for (int nt = 0; nt < 8; nt++)
        #pragma unroll
        for (int e = 0; e < 4; e++) acc[nt][e] = 0.f;

    #pragma unroll
    for (int ks = 0; ks < 8; ks++) {
        uint32_t a[4];
        ldsm_x4(a, aS_s + (uint32_t)(((wid*16 + (lane & 15)) * A1_STR
                          + ks*16 + ((lane >> 4) << 3)) * 2));
        #pragma unroll
        for (int np = 0; np < 4; np++) {
            uint32_t b[4];
            ldsm_x4_t(b, wS_s + (uint32_t)(((ks*16 + (lane & 15)) * W1_STR
                              + np*16 + ((lane >> 4) << 3)) * 2));
            mma_fp16(acc[np*2],     a, b[0], b[1]);
            mma_fp16(acc[np*2 + 1], a, b[2], b[3]);
        }
    }

    float s0 = 0.f, s1 = 0.f;
    #pragma unroll
    for (int nt = 0; nt < 8; nt++) {
        int j0 = nt*8 + (lane & 3)*2;
        float b1a = __ldg(b1 + j0), b1b = __ldg(b1 + j0 + 1);
        float w2a = __ldg(W2 + j0), w2b = __ldg(W2 + j0 + 1);
        s0 += tanhf(acc[nt][0] + b1a) * w2a + tanhf(acc[nt][1] + b1b) * w2b;
        s1 += tanhf(acc[nt][2] + b1a) * w2a + tanhf(acc[nt][3] + b1b) * w2b;
    }
    #pragma unroll
    for (int m = 1; m <= 2; m <<= 1) {
        s0 += __shfl_xor_sync(0xffffffffu, s0, m);
        s1 += __shfl_xor_sync(0xffffffffu, s1, m);
    }
    if ((lane & 3) == 0) {
        float bb2 = __ldg(b2);
        int r = lane >> 2;
        int tok = tok0 + wid*16 + r;
        if (tok < B)     g_p[tok]     = expf(s0 + bb2);
        if (tok + 8 < B) g_p[tok + 8] = expf(s1 + bb2);
    }
}

// ---------------------------------------------------------------------------
// Kernel 2: round-7 version verbatim (best measured). split-K fp16 MMA,
// KCHUNK=32, one 512-thread CTA per split covers all 256 l, register
// prefetch, double-buffered smem, 1 sync/chunk. warp = 32 l x 64 d.
// ---------------------------------------------------------------------------
#define MA_STR 40    // 32 k + 8 pad (halves)
#define G_STR  136   // 128 d + 8 pad (halves)
#define MA_HALVES (LTOT*MA_STR)   // 10240
#define G_HALVES  (KCHUNK*G_STR)  // 4352
#define SM2_BYTES ((2*MA_HALVES + 2*G_HALVES) * 2 + LTOT*8*4)

__global__ __launch_bounds__(512, 1) void k2_mma(
    const float* __restrict__ feats, const float* __restrict__ mask,
    int B, int chunksPerSplit)
{
    extern __shared__ char smraw[];
    __half* mA  = (__half*)smraw;                    // 2 x [256 l][40]
    __half* fS  = mA + 2*MA_HALVES;                  // 2 x [32 k][136]
    float*  zsm = (float*)(fS + 2*G_HALVES);         // [256][8]

    int tid  = threadIdx.x;
    int y    = blockIdx.x;
    int wid  = tid >> 5, lane = tid & 31;
    int wm   = wid & 7, wn = wid >> 3;

    float acc[2][8][4];
    #pragma unroll
    for (int mt = 0; mt < 2; mt++)
        #pragma unroll
        for (int nt = 0; nt < 8; nt++)
            #pragma unroll
            for (int e = 0; e < 4; e++) acc[mt][nt][e] = 0.f;
    float zacc[4] = {0.f, 0.f, 0.f, 0.f};

    uint32_t mA_s = (uint32_t)__cvta_generic_to_shared(mA);
    uint32_t fS_s = (uint32_t)__cvta_generic_to_shared(fS);

    int mrow = tid >> 3, mc4 = tid & 7;      // mask: l rows mrow+64i, k-col mc4*4

    float4 m4[4], f4[2], p4;
    int kb0 = y * chunksPerSplit * KCHUNK;

    // prologue: chunk 0 regs
    {
        int gk = kb0 + mc4*4;
        p4 = (gk < B) ? *((const float4*)(g_p + gk)) : make_float4(0.f,0.f,0.f,0.f);
        #pragma unroll
        for (int i = 0; i < 4; i++)
            m4[i] = (gk < B) ? *((const float4*)(mask + (size_t)(mrow + i*64)*B + gk))
                             : make_float4(0.f, 0.f, 0.f, 0.f);
        #pragma unroll
        for (int i = 0; i < 2; i++) {
            int idx = tid + i*512;
            int tok = kb0 + (idx >> 5);
            f4[i] = (tok < B) ? ((const float4*)(feats + (size_t)tok*DDIM))[idx & 31]
                              : make_float4(0.f, 0.f, 0.f, 0.f);
        }
    }

    for (int c = 0; c < chunksPerSplit; c++) {
        __half* mA_c = mA + (c & 1) * MA_HALVES;
        __half* fS_c = fS + (c & 1) * G_HALVES;

        // stage mp(c) = mask*p -> fp16; Z fused
        #pragma unroll
        for (int i = 0; i < 4; i++) {
            float4 v = m4[i];
            float mpx = v.x*p4.x, mpy = v.y*p4.y, mpz = v.z*p4.z, mpw = v.w*p4.w;
            zacc[i] += mpx + mpy + mpz + mpw;
            *(uint2*)(mA_c + (mrow + i*64)*MA_STR + mc4*4) = pack_half4(mpx, mpy, mpz, mpw);
        }
        // stage feats(c) fp32 regs -> fp16
        #pragma unroll
        for (int i = 0; i < 2; i++) {
            int idx = tid + i*512;
            *(uint2*)(fS_c + (idx >> 5)*G_STR + (idx & 31)*4)
                = pack_half4(f4[i].x, f4[i].y, f4[i].z, f4[i].w);
        }

        // prefetch chunk c+1 regs
        if (c + 1 < chunksPerSplit) {
            int kb2 = kb0 + (c + 1)*KCHUNK;
            int gk = kb2 + mc4*4;
            p4 = (gk < B) ? *((const float4*)(g_p + gk)) : make_float4(0.f,0.f,0.f,0.f);
            #pragma unroll
            for (int i = 0; i < 4; i++)
                m4[i] = (gk < B) ? *((const float4*)(mask + (size_t)(mrow + i*64)*B + gk))
                                 : make_float4(0.f, 0.f, 0.f, 0.f);
            #pragma unroll
            for (int i = 0; i < 2; i++) {
                int idx = tid + i*512;
                int tok = kb2 + (idx >> 5);
                f4[i] = (tok < B) ? ((const float4*)(feats + (size_t)tok*DDIM))[idx & 31]
                                  : make_float4(0.f, 0.f, 0.f, 0.f);
            }
        }
        __syncthreads();   // staged buffers visible; MMA(c-1) done

        // MMA over chunk c
        uint32_t mA_b = mA_s + (uint32_t)((c & 1) * MA_HALVES * 2);
        uint32_t fS_b = fS_s + (uint32_t)((c & 1) * G_HALVES * 2);
        #pragma unroll
        for (int ks = 0; ks < 2; ks++) {
            uint32_t a[2][4];
            #pragma unroll
            for (int mt = 0; mt < 2; mt++)
                ldsm_x4(a[mt], mA_b + (uint32_t)(((wm*32 + mt*16 + (lane & 15)) * MA_STR
                                 + ks*16 + ((lane >> 4) << 3)) * 2));
            #pragma unroll
            for (int np = 0; np < 4; np++) {
                uint32_t b[4];
                ldsm_x4_t(b, fS_b + (uint32_t)(((ks*16 + (lane & 15)) * G_STR
                                 + wn*64 + np*16 + ((lane >> 4) << 3)) * 2));
                #pragma unroll
                for (int mt = 0; mt < 2; mt++) {
                    mma_fp16(acc[mt][np*2],     a[mt], b[0], b[1]);
                    mma_fp16(acc[mt][np*2 + 1], a[mt], b[2], b[3]);
                }
            }
        }
    }

    // deterministic Z reduction
    __syncthreads();
    #pragma unroll
    for (int i = 0; i < 4; i++)
        zsm[(mrow + i*64)*8 + mc4] = zacc[i];
    __syncthreads();
    if (tid < LTOT) {
        float z = 0.f;
        #pragma unroll
        for (int j = 0; j < 8; j++) z += zsm[tid*8 + j];
        g_zpart[y*LTOT + tid] = z;
    }

    // write numerator partials
    #pragma unroll
    for (int mt = 0; mt < 2; mt++) {
        #pragma unroll
        for (int nt = 0; nt < 8; nt++) {
            int grow = wm*32 + mt*16 + (lane >> 2);
            int gcol = wn*64 + nt*8 + (lane & 3)*2;
            size_t b0 = ((size_t)y*LTOT + grow) * DDIM + gcol;
            size_t b1 = ((size_t)y*LTOT + grow + 8) * DDIM + gcol;
            *(float2*)(g_part + b0) = make_float2(acc[mt][nt][0], acc[mt][nt][1]);
            *(float2*)(g_part + b1) = make_float2(acc[mt][nt][2], acc[mt][nt][3]);
        }
    }
}

// ---------------------------------------------------------------------------
// Kernel 3: parallel reduce, FULL unroll -> all 37 loads in flight.
// ---------------------------------------------------------------------------
__global__ __launch_bounds__(512, 2) void k3_reduce(float* __restrict__ out)
{
    __shared__ float nsm[4][DDIM];
    __shared__ float zsm4[4];

    int l = blockIdx.x;
    int tid = threadIdx.x;
    int g = tid >> 7;
    int d = tid & 127;

    const float* pbase = g_part + ((size_t)(g*37)*LTOT + l) * DDIM + d;
    const float* zbase = g_zpart + (g*37)*LTOT + l;

    float n0 = 0.f, n1 = 0.f, z0 = 0.f, z1 = 0.f;
    #pragma unroll
    for (int yy = 0; yy < 37; yy += 2) {
        n0 += pbase[(size_t)yy * LTOT * DDIM];
        z0 += zbase[yy * LTOT];
    }
    #pragma unroll
    for (int yy = 1; yy < 37; yy += 2) {
        n1 += pbase[(size_t)yy * LTOT * DDIM];
        z1 += zbase[yy * LTOT];
    }
    nsm[g][d] = n0 + n1;
    if (d == 0) zsm4[g] = z0 + z1;
    __syncthreads();

    if (g == 0) {
        float n = nsm[0][d] + nsm[1][d] + nsm[2][d] + nsm[3][d];
        float zz = zsm4[0] + zsm4[1] + zsm4[2] + zsm4[3];
        out[l*DDIM + d] = (zz > 0.f) ? n / zz : 0.f;
    }
}

// ---------------------------------------------------------------------------
extern "C" void kernel_launch(void* const* d_in, const int* in_sizes, int n_in,
                              void* d_out, int out_size)
{
    const float* feats = (const float*)d_in[0];
    const float* mask  = (const float*)d_in[1];
    const float* W1    = (const float*)d_in[2];
    const float* b1    = (const float*)d_in[3];
    const float* W2    = (const float*)d_in[4];
    const float* b2    = (const float*)d_in[5];
    float* out = (float*)d_out;

    int B = in_sizes[0] / DDIM;           // 200000
    int totalChunks = (B + KCHUNK - 1) / KCHUNK;
    int cps = (totalChunks + SPLITK - 1) / SPLITK;

    cudaFuncSetAttribute(k1_logits, cudaFuncAttributeMaxDynamicSharedMemorySize, SM1_BYTES);
    cudaFuncSetAttribute(k2_mma,    cudaFuncAttributeMaxDynamicSharedMemorySize, SM2_BYTES);

    int g1 = (B + 127) / 128;
    k1_logits<<<g1, 256, SM1_BYTES>>>(feats, W1, b1, W2, b2, B);

    k2_mma<<<SPLITK, 512, SM2_BYTES>>>(feats, mask, B, cps);

    k3_reduce<<<LTOT, 512>>>(out);
}